// round 8
// baseline (speedup 1.0000x reference)
#include <cuda_runtime.h>
#include <cuda_bf16.h>
#include <math.h>
#include <stdint.h>

#define B_   8
#define PLEN 2048
#define QLEN 1024
#define HID  1024

// Scratch (__device__ globals: allocation-free rule)
__device__ float g_pkey[(size_t)B_ * PLEN * HID];   // 64 MB
__device__ float g_qkey[(size_t)B_ * QLEN * HID];   // 32 MB
__device__ float g_qT  [(size_t)B_ * HID  * QLEN];  // 32 MB

// ---------------------------------------------------------------------------
// helpers
// ---------------------------------------------------------------------------
__device__ __forceinline__ uint32_t smem_u32(const void* p) {
    return (uint32_t)__cvta_generic_to_shared(p);
}

// split two fp32 into packed bf16x2 (hi plane, lo plane); element0 in low half
__device__ __forceinline__ void split2(float x0, float x1,
                                       uint32_t& hi, uint32_t& lo) {
    __nv_bfloat16 h0 = __float2bfloat16_rn(x0);
    __nv_bfloat16 h1 = __float2bfloat16_rn(x1);
    float r0 = x0 - __bfloat162float(h0);
    float r1 = x1 - __bfloat162float(h1);
    __nv_bfloat16 l0 = __float2bfloat16_rn(r0);
    __nv_bfloat16 l1 = __float2bfloat16_rn(r1);
    hi = ((uint32_t)__bfloat16_as_ushort(h1) << 16) | __bfloat16_as_ushort(h0);
    lo = ((uint32_t)__bfloat16_as_ushort(l1) << 16) | __bfloat16_as_ushort(l0);
}

__device__ __forceinline__ void ldsm_x4(uint32_t r[4], uint32_t addr) {
    asm volatile("ldmatrix.sync.aligned.m8n8.x4.shared.b16 {%0,%1,%2,%3}, [%4];"
                 : "=r"(r[0]), "=r"(r[1]), "=r"(r[2]), "=r"(r[3]) : "r"(addr));
}

__device__ __forceinline__ void mma_bf16(float c[4], const uint32_t a[4],
                                         uint32_t b0, uint32_t b1) {
    asm volatile(
        "mma.sync.aligned.m16n8k16.row.col.f32.bf16.bf16.f32 "
        "{%0,%1,%2,%3}, {%4,%5,%6,%7}, {%8,%9}, {%0,%1,%2,%3};"
        : "+f"(c[0]), "+f"(c[1]), "+f"(c[2]), "+f"(c[3])
        : "r"(a[0]), "r"(a[1]), "r"(a[2]), "r"(a[3]), "r"(b0), "r"(b1));
}

// ---------------------------------------------------------------------------
// 3xBF16 NT GEMM: C[m,n] = (opt relu) sum_k A[m,k]*B[n,k], fp32 in/out.
// CTA tile 128x128, BK=64, THREE-stage split-bf16 smem pipeline.
// 16 warps: 4(M) x 4(N); warp tile 32x32. One barrier per 64-K chunk.
// Iteration order: SPLITSTORE(c+1) -> LOADRAW(c+2) -> MMA(c) -> barrier,
// so the producer tail overlaps the ldsm ramp instead of trailing the MMAs.
// ---------------------------------------------------------------------------
#define STRD   144      // bytes per smem row: 64 bf16 (128B) + 16B pad
#define PLANE  18432    // 128 rows * 144
#define OFF_AH 0
#define OFF_AL PLANE
#define OFF_BH (2 * PLANE)
#define OFF_BL (3 * PLANE)
#define STAGE  (4 * PLANE)      // 73728
#define NSTAGE 3
#define GSMEM  (NSTAGE * STAGE) // 221184

__global__ __launch_bounds__(512, 1) void gemm_3xbf16(
    const float* __restrict__ A, const float* __restrict__ Bm,
    float* __restrict__ C, int K, int ldc, int relu,
    size_t sA, size_t sB, size_t sC)
{
    extern __shared__ __align__(128) char smem[];
    const uint32_t sbase = smem_u32(smem);
    const int tid  = threadIdx.x;
    const int lane = tid & 31;
    const int wid  = tid >> 5;
    const int m0 = blockIdx.y * 128;
    const int n0 = blockIdx.x * 128;
    A  += (size_t)blockIdx.z * sA;
    Bm += (size_t)blockIdx.z * sB;
    C  += (size_t)blockIdx.z * sC;

    // producer indexing: 128 rows x 16 float4 per operand; 4+4 loads/thread
    uint32_t gofsA[4], gofsB[4], stsAB[4];
    #pragma unroll
    for (int i = 0; i < 4; i++) {
        int lin = tid + 512 * i;
        int row = lin >> 4, c4 = lin & 15;
        gofsA[i] = (uint32_t)((m0 + row) * K + c4 * 4) * 4u;
        gofsB[i] = (uint32_t)((n0 + row) * K + c4 * 4) * 4u;
        stsAB[i] = (uint32_t)(row * STRD + c4 * 8);
    }

    float4 va[4], vb[4];            // raw staged gmem data (one chunk ahead)
    const char* Ab = (const char*)A;
    const char* Bb = (const char*)Bm;

    auto LOADRAW = [&](int c) {     // LDG only
        uint32_t kb = (uint32_t)c * 256u;   // 64 floats
        #pragma unroll
        for (int i = 0; i < 4; i++) va[i] = *(const float4*)(Ab + gofsA[i] + kb);
        #pragma unroll
        for (int i = 0; i < 4; i++) vb[i] = *(const float4*)(Bb + gofsB[i] + kb);
    };
    auto SPLITSTORE = [&](int st_idx) {  // cvt/sub + STS from staged regs
        char* st = smem + st_idx * STAGE;
        #pragma unroll
        for (int i = 0; i < 4; i++) {
            uint2 h, l;
            split2(va[i].x, va[i].y, h.x, l.x);
            split2(va[i].z, va[i].w, h.y, l.y);
            *(uint2*)(st + OFF_AH + stsAB[i]) = h;
            *(uint2*)(st + OFF_AL + stsAB[i]) = l;
        }
        #pragma unroll
        for (int i = 0; i < 4; i++) {
            uint2 h, l;
            split2(vb[i].x, vb[i].y, h.x, l.x);
            split2(vb[i].z, vb[i].w, h.y, l.y);
            *(uint2*)(st + OFF_BH + stsAB[i]) = h;
            *(uint2*)(st + OFF_BL + stsAB[i]) = l;
        }
    };

    // consumer indexing: warp grid 4(M) x 4(N), warp tile 32x32
    const int wm = (wid & 3) * 32;
    const int wn = (wid >> 2) * 32;
    const int a_row = (lane & 15);
    const int a_kc  = (lane >> 4) * 8;
    const int b_row = ((lane >> 4) << 3) + (lane & 7);
    const int b_kc  = ((lane >> 3) & 1) * 8;

    float acc[2][4][4] = {};   // [mt][nb*2+nt][frag]

    const int nCh = K / 64;

    // prologue: fill stage 0, stage 1's data into regs
    LOADRAW(0); SPLITSTORE(0);
    if (nCh > 1) LOADRAW(1);
    __syncthreads();

    int stage_c = 0;           // stage holding chunk c
    #pragma unroll 1
    for (int c = 0; c < nCh; ++c) {
        // 1) store chunk c+1 (regs loaded at iter c-1 / prologue)
        if (c + 1 < nCh) {
            int st_next = stage_c + 1; if (st_next == NSTAGE) st_next = 0;
            SPLITSTORE(st_next);
        }
        // 2) start LDGs for chunk c+2
        if (c + 2 < nCh) LOADRAW(c + 2);

        // 3) MMAs on chunk c
        const uint32_t stb = sbase + stage_c * STAGE;
        #pragma unroll
        for (int kk = 0; kk < 64; kk += 16) {
            uint32_t ah[2][4], al[2][4], bh[2][4], bl[2][4];
            #pragma unroll
            for (int mt = 0; mt < 2; mt++) {
                uint32_t ro = (uint32_t)((wm + mt * 16 + a_row) * STRD +
                                         (kk + a_kc) * 2);
                ldsm_x4(ah[mt], stb + OFF_AH + ro);
                ldsm_x4(al[mt], stb + OFF_AL + ro);
            }
            #pragma unroll
            for (int nb = 0; nb < 2; nb++) {
                uint32_t ro = (uint32_t)((wn + nb * 16 + b_row) * STRD +
                                         (kk + b_kc) * 2);
                ldsm_x4(bh[nb], stb + OFF_BH + ro);
                ldsm_x4(bl[nb], stb + OFF_BL + ro);
            }
            // pass 1: hi*hi — 8 independent MMAs
            #pragma unroll
            for (int mt = 0; mt < 2; mt++)
                #pragma unroll
                for (int nb = 0; nb < 2; nb++)
                    #pragma unroll
                    for (int nt = 0; nt < 2; nt++)
                        mma_bf16(acc[mt][nb * 2 + nt], ah[mt],
                                 bh[nb][nt * 2], bh[nb][nt * 2 + 1]);
            // pass 2: hi*lo
            #pragma unroll
            for (int mt = 0; mt < 2; mt++)
                #pragma unroll
                for (int nb = 0; nb < 2; nb++)
                    #pragma unroll
                    for (int nt = 0; nt < 2; nt++)
                        mma_bf16(acc[mt][nb * 2 + nt], ah[mt],
                                 bl[nb][nt * 2], bl[nb][nt * 2 + 1]);
            // pass 3: lo*hi
            #pragma unroll
            for (int mt = 0; mt < 2; mt++)
                #pragma unroll
                for (int nb = 0; nb < 2; nb++)
                    #pragma unroll
                    for (int nt = 0; nt < 2; nt++)
                        mma_bf16(acc[mt][nb * 2 + nt], al[mt],
                                 bh[nb][nt * 2], bh[nb][nt * 2 + 1]);
        }
        __syncthreads();
        if (++stage_c == NSTAGE) stage_c = 0;
    }

    // epilogue
    const int g = lane >> 2, cc2 = (lane & 3) * 2;
    #pragma unroll
    for (int mt = 0; mt < 2; mt++) {
        #pragma unroll
        for (int j = 0; j < 4; j++) {
            int row = m0 + wm + mt * 16 + g;
            int col = n0 + wn + j * 8 + cc2;
            float* a4 = acc[mt][j];
            if (relu) {
                a4[0] = fmaxf(a4[0], 0.f); a4[1] = fmaxf(a4[1], 0.f);
                a4[2] = fmaxf(a4[2], 0.f); a4[3] = fmaxf(a4[3], 0.f);
            }
            *(float2*)(C + (size_t)row * ldc + col)       = make_float2(a4[0], a4[1]);
            *(float2*)(C + (size_t)(row + 8) * ldc + col) = make_float2(a4[2], a4[3]);
        }
    }
}

// ---------------------------------------------------------------------------
// q[b][j][h] -> qT[b][h][j]
// ---------------------------------------------------------------------------
__global__ void transpose_q(const float* __restrict__ q, float* __restrict__ qT)
{
    __shared__ float tile[32][33];
    const int b = blockIdx.z;
    const int j0 = blockIdx.x * 32, h0 = blockIdx.y * 32;
    const float* qb = q + (size_t)b * QLEN * HID;
    float* tb = qT + (size_t)b * HID * QLEN;
    #pragma unroll
    for (int r = threadIdx.y; r < 32; r += 8)
        tile[r][threadIdx.x] = qb[(size_t)(j0 + r) * HID + h0 + threadIdx.x];
    __syncthreads();
    #pragma unroll
    for (int r = threadIdx.y; r < 32; r += 8)
        tb[(size_t)(h0 + r) * QLEN + j0 + threadIdx.x] = tile[threadIdx.x][r];
}

// ---------------------------------------------------------------------------
// In-place row softmax over Q with q_mask (True = pad -> -inf).
// ---------------------------------------------------------------------------
__global__ __launch_bounds__(256) void softmax_rows(
    float* __restrict__ sc, const unsigned char* __restrict__ qmask)
{
    const int row = blockIdx.x;
    const int b   = row / PLEN;
    float* s = sc + (size_t)row * QLEN;
    const unsigned char* m = qmask + (size_t)b * QLEN;

    const int t = threadIdx.x;
    float v[4];
    float mx = -INFINITY;
    #pragma unroll
    for (int i = 0; i < 4; i++) {
        int idx = t + i * 256;
        float x = s[idx];
        if (m[idx]) x = -INFINITY;
        v[i] = x;
        mx = fmaxf(mx, x);
    }

    __shared__ float warpred[8];
    __shared__ float bcast;

    #pragma unroll
    for (int o = 16; o; o >>= 1) mx = fmaxf(mx, __shfl_xor_sync(0xffffffffu, mx, o));
    if ((t & 31) == 0) warpred[t >> 5] = mx;
    __syncthreads();
    if (t == 0) {
        float r = warpred[0];
        #pragma unroll
        for (int w = 1; w < 8; w++) r = fmaxf(r, warpred[w]);
        bcast = r;
    }
    __syncthreads();
    mx = bcast;

    float sum = 0.0f;
    #pragma unroll
    for (int i = 0; i < 4; i++) { v[i] = expf(v[i] - mx); sum += v[i]; }
    __syncthreads();

    #pragma unroll
    for (int o = 16; o; o >>= 1) sum += __shfl_xor_sync(0xffffffffu, sum, o);
    if ((t & 31) == 0) warpred[t >> 5] = sum;
    __syncthreads();
    if (t == 0) {
        float r = 0.0f;
        #pragma unroll
        for (int w = 0; w < 8; w++) r += warpred[w];
        bcast = r;
    }
    __syncthreads();
    const float inv = 1.0f / bcast;

    #pragma unroll
    for (int i = 0; i < 4; i++)
        s[t + i * 256] = v[i] * inv;
}

// ---------------------------------------------------------------------------
extern "C" void kernel_launch(void* const* d_in, const int* in_sizes, int n_in,
                              void* d_out, int out_size)
{
    (void)in_sizes; (void)n_in; (void)out_size;
    const float*         k     = (const float*)d_in[0];          // [B, P, H]
    const float*         q     = (const float*)d_in[1];          // [B, Q, H]
    const unsigned char* qmask = (const unsigned char*)d_in[2];  // [B, Q] bool
    const float*         Wk    = (const float*)d_in[3];          // [H, H]
    const float*         Wq    = (const float*)d_in[4];          // [H, H]

    float* ctx    = (float*)d_out;                               // [B, P, H]
    float* alphas = ctx + (size_t)B_ * PLEN * HID;               // [B, P, Q]

    float *pkey, *qkey, *qT;
    cudaGetSymbolAddress((void**)&pkey, g_pkey);
    cudaGetSymbolAddress((void**)&qkey, g_qkey);
    cudaGetSymbolAddress((void**)&qT,   g_qT);

    static int smem_set = 0;
    if (!smem_set) {
        cudaFuncSetAttribute(gemm_3xbf16,
                             cudaFuncAttributeMaxDynamicSharedMemorySize, GSMEM);
        smem_set = 1;
    }

    // 0) qT[b] = q[b]^T
    transpose_q<<<dim3(QLEN / 32, HID / 32, B_), dim3(32, 8)>>>(q, qT);

    // 1) p_key = relu(k @ Wk^T)
    gemm_3xbf16<<<dim3(HID / 128, (B_ * PLEN) / 128, 1), 512, GSMEM>>>(
        k, Wk, pkey, HID, HID, 1, 0, 0, 0);

    // 2) q_key = relu(q @ Wq^T)
    gemm_3xbf16<<<dim3(HID / 128, (B_ * QLEN) / 128, 1), 512, GSMEM>>>(
        q, Wq, qkey, HID, HID, 1, 0, 0, 0);

    // 3) scores[b] = p_key[b] @ q_key[b]^T  -> raw into alphas region
    gemm_3xbf16<<<dim3(QLEN / 128, PLEN / 128, B_), 512, GSMEM>>>(
        pkey, qkey, alphas, HID, QLEN, 0,
        (size_t)PLEN * HID, (size_t)QLEN * HID, (size_t)PLEN * QLEN);

    // 4) softmax in place
    softmax_rows<<<B_ * PLEN, 256>>>(alphas, qmask);

    // 5) ctx[b] = alphas[b] @ q[b] == alphas[b] @ (qT[b])^T  (NT)
    gemm_3xbf16<<<dim3(HID / 128, PLEN / 128, B_), 512, GSMEM>>>(
        alphas, qT, ctx, QLEN, HID, 0,
        (size_t)PLEN * QLEN, (size_t)HID * QLEN, (size_t)PLEN * HID);
}

// round 9
// speedup vs baseline: 1.3616x; 1.3616x over previous
#include <cuda_runtime.h>
#include <cuda_bf16.h>
#include <math.h>
#include <stdint.h>

#define B_   8
#define PLEN 2048
#define QLEN 1024
#define HID  1024

// Scratch (__device__ globals: allocation-free rule)
__device__ float g_pkey[(size_t)B_ * PLEN * HID];   // 64 MB
__device__ float g_qkey[(size_t)B_ * QLEN * HID];   // 32 MB
__device__ float g_qT  [(size_t)B_ * HID  * QLEN];  // 32 MB

// ---------------------------------------------------------------------------
// helpers
// ---------------------------------------------------------------------------
__device__ __forceinline__ uint32_t smem_u32(const void* p) {
    return (uint32_t)__cvta_generic_to_shared(p);
}

// split two fp32 into packed bf16x2 (hi plane, lo plane) using packed cvt.
// element0 in low half.
__device__ __forceinline__ void split2(float x0, float x1,
                                       uint32_t& hi, uint32_t& lo) {
    uint32_t h;
    asm("cvt.rn.bf16x2.f32 %0, %1, %2;" : "=r"(h) : "f"(x1), "f"(x0));
    float h0 = __uint_as_float(h << 16);           // bf16 -> f32 via shift
    float h1 = __uint_as_float(h & 0xffff0000u);
    uint32_t l;
    asm("cvt.rn.bf16x2.f32 %0, %1, %2;" : "=r"(l) : "f"(x1 - h1), "f"(x0 - h0));
    hi = h; lo = l;
}

__device__ __forceinline__ void ldsm_x4(uint32_t r[4], uint32_t addr) {
    asm volatile("ldmatrix.sync.aligned.m8n8.x4.shared.b16 {%0,%1,%2,%3}, [%4];"
                 : "=r"(r[0]), "=r"(r[1]), "=r"(r[2]), "=r"(r[3]) : "r"(addr));
}

__device__ __forceinline__ void mma_bf16(float c[4], const uint32_t a[4],
                                         uint32_t b0, uint32_t b1) {
    asm volatile(
        "mma.sync.aligned.m16n8k16.row.col.f32.bf16.bf16.f32 "
        "{%0,%1,%2,%3}, {%4,%5,%6,%7}, {%8,%9}, {%0,%1,%2,%3};"
        : "+f"(c[0]), "+f"(c[1]), "+f"(c[2]), "+f"(c[3])
        : "r"(a[0]), "r"(a[1]), "r"(a[2]), "r"(a[3]), "r"(b0), "r"(b1));
}

// ---------------------------------------------------------------------------
// 3xBF16 NT GEMM: C[m,n] = (opt relu) sum_k A[m,k]*B[n,k], fp32 in/out.
// CTA tile 128x128, BK=64, TWO-stage split-bf16 smem pipeline (R7 skeleton).
// 16 warps: 4(M) x 4(N); warp tile 32x32. One barrier per 64-K chunk.
// SPLITSTORE for the next chunk is chopped into 4 pieces, one issued after
// each kk-step's MMA passes, so producer ALU/STS fills the MMA issue shadow.
// ---------------------------------------------------------------------------
#define STRD   144      // bytes per smem row: 64 bf16 (128B) + 16B pad
#define PLANE  18432    // 128 rows * 144
#define OFF_AH 0
#define OFF_AL PLANE
#define OFF_BH (2 * PLANE)
#define OFF_BL (3 * PLANE)
#define STAGE  (4 * PLANE)      // 73728
#define GSMEM  (2 * STAGE)      // 147456

__global__ __launch_bounds__(512, 1) void gemm_3xbf16(
    const float* __restrict__ A, const float* __restrict__ Bm,
    float* __restrict__ C, int K, int ldc, int relu,
    size_t sA, size_t sB, size_t sC)
{
    extern __shared__ __align__(128) char smem[];
    const uint32_t sbase = smem_u32(smem);
    const int tid  = threadIdx.x;
    const int lane = tid & 31;
    const int wid  = tid >> 5;
    const int m0 = blockIdx.y * 128;
    const int n0 = blockIdx.x * 128;
    A  += (size_t)blockIdx.z * sA;
    Bm += (size_t)blockIdx.z * sB;
    C  += (size_t)blockIdx.z * sC;

    // producer indexing: 128 rows x 16 float4 per operand; 4+4 loads/thread
    uint32_t gofsA[4], gofsB[4], stsAB[4];
    #pragma unroll
    for (int i = 0; i < 4; i++) {
        int lin = tid + 512 * i;
        int row = lin >> 4, c4 = lin & 15;
        gofsA[i] = (uint32_t)((m0 + row) * K + c4 * 4) * 4u;
        gofsB[i] = (uint32_t)((n0 + row) * K + c4 * 4) * 4u;
        stsAB[i] = (uint32_t)(row * STRD + c4 * 8);
    }

    float4 va[4], vb[4];            // raw staged gmem data
    const char* Ab = (const char*)A;
    const char* Bb = (const char*)Bm;

    auto LOADRAW = [&](int c) {     // LDG only
        uint32_t kb = (uint32_t)c * 256u;   // 64 floats
        #pragma unroll
        for (int i = 0; i < 4; i++) va[i] = *(const float4*)(Ab + gofsA[i] + kb);
        #pragma unroll
        for (int i = 0; i < 4; i++) vb[i] = *(const float4*)(Bb + gofsB[i] + kb);
    };
    // one quarter of the split+store work: operand pair i
    auto SPLITPIECE = [&](int s, int i) {
        char* st = smem + s * STAGE;
        uint2 h, l;
        split2(va[i].x, va[i].y, h.x, l.x);
        split2(va[i].z, va[i].w, h.y, l.y);
        *(uint2*)(st + OFF_AH + stsAB[i]) = h;
        *(uint2*)(st + OFF_AL + stsAB[i]) = l;
        split2(vb[i].x, vb[i].y, h.x, l.x);
        split2(vb[i].z, vb[i].w, h.y, l.y);
        *(uint2*)(st + OFF_BH + stsAB[i]) = h;
        *(uint2*)(st + OFF_BL + stsAB[i]) = l;
    };

    // consumer indexing: warp grid 4(M) x 4(N), warp tile 32x32
    const int wm = (wid & 3) * 32;
    const int wn = (wid >> 2) * 32;
    const int a_row = (lane & 15);
    const int a_kc  = (lane >> 4) * 8;
    const int b_row = ((lane >> 4) << 3) + (lane & 7);
    const int b_kc  = ((lane >> 3) & 1) * 8;

    float acc[2][4][4] = {};   // [mt][nb*2+nt][frag]

    const int nCh = K / 64;
    LOADRAW(0);
    #pragma unroll
    for (int i = 0; i < 4; i++) SPLITPIECE(0, i);
    __syncthreads();

    #pragma unroll 1
    for (int c = 0; c < nCh; ++c) {
        const int s = c & 1;
        const bool more = (c + 1) < nCh;
        if (more) LOADRAW(c + 1);   // LDGs in flight during MMAs

        const uint32_t stb = sbase + s * STAGE;
        #pragma unroll
        for (int kk = 0; kk < 64; kk += 16) {
            uint32_t ah[2][4], al[2][4], bh[2][4], bl[2][4];
            #pragma unroll
            for (int mt = 0; mt < 2; mt++) {
                uint32_t ro = (uint32_t)((wm + mt * 16 + a_row) * STRD +
                                         (kk + a_kc) * 2);
                ldsm_x4(ah[mt], stb + OFF_AH + ro);
                ldsm_x4(al[mt], stb + OFF_AL + ro);
            }
            #pragma unroll
            for (int nb = 0; nb < 2; nb++) {
                uint32_t ro = (uint32_t)((wn + nb * 16 + b_row) * STRD +
                                         (kk + b_kc) * 2);
                ldsm_x4(bh[nb], stb + OFF_BH + ro);
                ldsm_x4(bl[nb], stb + OFF_BL + ro);
            }
            // pass 1: hi*hi — 8 independent MMAs
            #pragma unroll
            for (int mt = 0; mt < 2; mt++)
                #pragma unroll
                for (int nb = 0; nb < 2; nb++)
                    #pragma unroll
                    for (int nt = 0; nt < 2; nt++)
                        mma_bf16(acc[mt][nb * 2 + nt], ah[mt],
                                 bh[nb][nt * 2], bh[nb][nt * 2 + 1]);
            // pass 2: hi*lo
            #pragma unroll
            for (int mt = 0; mt < 2; mt++)
                #pragma unroll
                for (int nb = 0; nb < 2; nb++)
                    #pragma unroll
                    for (int nt = 0; nt < 2; nt++)
                        mma_bf16(acc[mt][nb * 2 + nt], ah[mt],
                                 bl[nb][nt * 2], bl[nb][nt * 2 + 1]);
            // pass 3: lo*hi
            #pragma unroll
            for (int mt = 0; mt < 2; mt++)
                #pragma unroll
                for (int nb = 0; nb < 2; nb++)
                    #pragma unroll
                    for (int nt = 0; nt < 2; nt++)
                        mma_bf16(acc[mt][nb * 2 + nt], al[mt],
                                 bh[nb][nt * 2], bh[nb][nt * 2 + 1]);
            // interleaved producer piece for next chunk (buffer s^1 was
            // consumed at iter c-1; barrier between iters makes this safe)
            if (more) SPLITPIECE(s ^ 1, kk >> 4);
        }
        __syncthreads();
    }

    // epilogue
    const int g = lane >> 2, cc2 = (lane & 3) * 2;
    #pragma unroll
    for (int mt = 0; mt < 2; mt++) {
        #pragma unroll
        for (int j = 0; j < 4; j++) {
            int row = m0 + wm + mt * 16 + g;
            int col = n0 + wn + j * 8 + cc2;
            float* a4 = acc[mt][j];
            if (relu) {
                a4[0] = fmaxf(a4[0], 0.f); a4[1] = fmaxf(a4[1], 0.f);
                a4[2] = fmaxf(a4[2], 0.f); a4[3] = fmaxf(a4[3], 0.f);
            }
            *(float2*)(C + (size_t)row * ldc + col)       = make_float2(a4[0], a4[1]);
            *(float2*)(C + (size_t)(row + 8) * ldc + col) = make_float2(a4[2], a4[3]);
        }
    }
}

// ---------------------------------------------------------------------------
// q[b][j][h] -> qT[b][h][j]
// ---------------------------------------------------------------------------
__global__ void transpose_q(const float* __restrict__ q, float* __restrict__ qT)
{
    __shared__ float tile[32][33];
    const int b = blockIdx.z;
    const int j0 = blockIdx.x * 32, h0 = blockIdx.y * 32;
    const float* qb = q + (size_t)b * QLEN * HID;
    float* tb = qT + (size_t)b * HID * QLEN;
    #pragma unroll
    for (int r = threadIdx.y; r < 32; r += 8)
        tile[r][threadIdx.x] = qb[(size_t)(j0 + r) * HID + h0 + threadIdx.x];
    __syncthreads();
    #pragma unroll
    for (int r = threadIdx.y; r < 32; r += 8)
        tb[(size_t)(h0 + r) * QLEN + j0 + threadIdx.x] = tile[threadIdx.x][r];
}

// ---------------------------------------------------------------------------
// In-place row softmax over Q with q_mask (True = pad -> -inf).
// ---------------------------------------------------------------------------
__global__ __launch_bounds__(256) void softmax_rows(
    float* __restrict__ sc, const unsigned char* __restrict__ qmask)
{
    const int row = blockIdx.x;
    const int b   = row / PLEN;
    float* s = sc + (size_t)row * QLEN;
    const unsigned char* m = qmask + (size_t)b * QLEN;

    const int t = threadIdx.x;
    float v[4];
    float mx = -INFINITY;
    #pragma unroll
    for (int i = 0; i < 4; i++) {
        int idx = t + i * 256;
        float x = s[idx];
        if (m[idx]) x = -INFINITY;
        v[i] = x;
        mx = fmaxf(mx, x);
    }

    __shared__ float warpred[8];
    __shared__ float bcast;

    #pragma unroll
    for (int o = 16; o; o >>= 1) mx = fmaxf(mx, __shfl_xor_sync(0xffffffffu, mx, o));
    if ((t & 31) == 0) warpred[t >> 5] = mx;
    __syncthreads();
    if (t == 0) {
        float r = warpred[0];
        #pragma unroll
        for (int w = 1; w < 8; w++) r = fmaxf(r, warpred[w]);
        bcast = r;
    }
    __syncthreads();
    mx = bcast;

    float sum = 0.0f;
    #pragma unroll
    for (int i = 0; i < 4; i++) { v[i] = expf(v[i] - mx); sum += v[i]; }
    __syncthreads();

    #pragma unroll
    for (int o = 16; o; o >>= 1) sum += __shfl_xor_sync(0xffffffffu, sum, o);
    if ((t & 31) == 0) warpred[t >> 5] = sum;
    __syncthreads();
    if (t == 0) {
        float r = 0.0f;
        #pragma unroll
        for (int w = 0; w < 8; w++) r += warpred[w];
        bcast = r;
    }
    __syncthreads();
    const float inv = 1.0f / bcast;

    #pragma unroll
    for (int i = 0; i < 4; i++)
        s[t + i * 256] = v[i] * inv;
}

// ---------------------------------------------------------------------------
extern "C" void kernel_launch(void* const* d_in, const int* in_sizes, int n_in,
                              void* d_out, int out_size)
{
    (void)in_sizes; (void)n_in; (void)out_size;
    const float*         k     = (const float*)d_in[0];          // [B, P, H]
    const float*         q     = (const float*)d_in[1];          // [B, Q, H]
    const unsigned char* qmask = (const unsigned char*)d_in[2];  // [B, Q] bool
    const float*         Wk    = (const float*)d_in[3];          // [H, H]
    const float*         Wq    = (const float*)d_in[4];          // [H, H]

    float* ctx    = (float*)d_out;                               // [B, P, H]
    float* alphas = ctx + (size_t)B_ * PLEN * HID;               // [B, P, Q]

    float *pkey, *qkey, *qT;
    cudaGetSymbolAddress((void**)&pkey, g_pkey);
    cudaGetSymbolAddress((void**)&qkey, g_qkey);
    cudaGetSymbolAddress((void**)&qT,   g_qT);

    static int smem_set = 0;
    if (!smem_set) {
        cudaFuncSetAttribute(gemm_3xbf16,
                             cudaFuncAttributeMaxDynamicSharedMemorySize, GSMEM);
        smem_set = 1;
    }

    // 0) qT[b] = q[b]^T
    transpose_q<<<dim3(QLEN / 32, HID / 32, B_), dim3(32, 8)>>>(q, qT);

    // 1) p_key = relu(k @ Wk^T)
    gemm_3xbf16<<<dim3(HID / 128, (B_ * PLEN) / 128, 1), 512, GSMEM>>>(
        k, Wk, pkey, HID, HID, 1, 0, 0, 0);

    // 2) q_key = relu(q @ Wq^T)
    gemm_3xbf16<<<dim3(HID / 128, (B_ * QLEN) / 128, 1), 512, GSMEM>>>(
        q, Wq, qkey, HID, HID, 1, 0, 0, 0);

    // 3) scores[b] = p_key[b] @ q_key[b]^T  -> raw into alphas region
    gemm_3xbf16<<<dim3(QLEN / 128, PLEN / 128, B_), 512, GSMEM>>>(
        pkey, qkey, alphas, HID, QLEN, 0,
        (size_t)PLEN * HID, (size_t)QLEN * HID, (size_t)PLEN * QLEN);

    // 4) softmax in place
    softmax_rows<<<B_ * PLEN, 256>>>(alphas, qmask);

    // 5) ctx[b] = alphas[b] @ q[b] == alphas[b] @ (qT[b])^T  (NT)
    gemm_3xbf16<<<dim3(HID / 128, PLEN / 128, B_), 512, GSMEM>>>(
        alphas, qT, ctx, QLEN, HID, 0,
        (size_t)PLEN * QLEN, (size_t)HID * QLEN, (size_t)PLEN * HID);
}

// round 10
// speedup vs baseline: 1.4009x; 1.0289x over previous
#include <cuda_runtime.h>
#include <cuda_bf16.h>
#include <math.h>
#include <stdint.h>

#define B_   8
#define PLEN 2048
#define QLEN 1024
#define HID  1024

// Scratch (__device__ globals: allocation-free rule)
__device__ float g_pkey[(size_t)B_ * PLEN * HID];   // 64 MB
__device__ float g_qkey[(size_t)B_ * QLEN * HID];   // 32 MB
__device__ float g_qT  [(size_t)B_ * HID  * QLEN];  // 32 MB

// ---------------------------------------------------------------------------
// helpers
// ---------------------------------------------------------------------------
__device__ __forceinline__ uint32_t smem_u32(const void* p) {
    return (uint32_t)__cvta_generic_to_shared(p);
}

// split two fp32 into packed bf16x2 (hi plane, lo plane); element0 in low half
__device__ __forceinline__ void split2(float x0, float x1,
                                       uint32_t& hi, uint32_t& lo) {
    uint32_t h;
    asm("cvt.rn.bf16x2.f32 %0, %1, %2;" : "=r"(h) : "f"(x1), "f"(x0));
    float h0 = __uint_as_float(h << 16);           // bf16 -> f32 via shift
    float h1 = __uint_as_float(h & 0xffff0000u);
    uint32_t l;
    asm("cvt.rn.bf16x2.f32 %0, %1, %2;" : "=r"(l) : "f"(x1 - h1), "f"(x0 - h0));
    hi = h; lo = l;
}

__device__ __forceinline__ void ldsm_x4(uint32_t r[4], uint32_t addr) {
    asm volatile("ldmatrix.sync.aligned.m8n8.x4.shared.b16 {%0,%1,%2,%3}, [%4];"
                 : "=r"(r[0]), "=r"(r[1]), "=r"(r[2]), "=r"(r[3]) : "r"(addr));
}

__device__ __forceinline__ void mma_bf16(float c[4], const uint32_t a[4],
                                         uint32_t b0, uint32_t b1) {
    asm volatile(
        "mma.sync.aligned.m16n8k16.row.col.f32.bf16.bf16.f32 "
        "{%0,%1,%2,%3}, {%4,%5,%6,%7}, {%8,%9}, {%0,%1,%2,%3};"
        : "+f"(c[0]), "+f"(c[1]), "+f"(c[2]), "+f"(c[3])
        : "r"(a[0]), "r"(a[1]), "r"(a[2]), "r"(a[3]), "r"(b0), "r"(b1));
}

// ---------------------------------------------------------------------------
// 3xBF16 NT GEMM, warp-specialized.
// C[m,n] = (opt relu) sum_k A[m,k]*B[n,k], fp32 in/out.
// CTA tile 128x128, BK=64, two-stage split-bf16 smem pipeline.
// 640 threads: warps 0-15 consumers (4Mx4N grid, 32x32 warp tile, pure
// ldsm+MMA); warps 16-19 producers (LDG -> split -> STS for next chunk,
// double-buffered rounds). One barrier per 64-K chunk.
// ---------------------------------------------------------------------------
#define STRD   144      // bytes per smem row: 64 bf16 (128B) + 16B pad
#define PLANE  18432    // 128 rows * 144
#define OFF_AH 0
#define OFF_AL PLANE
#define OFF_BH (2 * PLANE)
#define OFF_BL (3 * PLANE)
#define STAGE  (4 * PLANE)      // 73728
#define GSMEM  (2 * STAGE)      // 147456
#define NTHREADS 640

__global__ __launch_bounds__(NTHREADS, 1) void gemm_3xbf16(
    const float* __restrict__ A, const float* __restrict__ Bm,
    float* __restrict__ C, int K, int ldc, int relu,
    size_t sA, size_t sB, size_t sC)
{
    extern __shared__ __align__(128) char smem[];
    const uint32_t sbase = smem_u32(smem);
    const int tid  = threadIdx.x;
    const int lane = tid & 31;
    const int wid  = tid >> 5;
    const int m0 = blockIdx.y * 128;
    const int n0 = blockIdx.x * 128;
    A  += (size_t)blockIdx.z * sA;
    Bm += (size_t)blockIdx.z * sB;
    C  += (size_t)blockIdx.z * sC;

    const int nCh = K / 64;

    if (wid >= 16) {
        // ===================== PRODUCER (warps 16-19, 128 threads) =========
        const int pt = tid - 512;           // 0..127
        const int prow = pt >> 4;           // 0..7
        const int pc4  = pt & 15;           // 0..15 (float4 column)
        // element offsets (floats) for round r, sub j: row = r*32 + 8*j + prow
        const char* Ab = (const char*)(A  + (size_t)(m0 + prow) * K + pc4 * 4);
        const char* Bb = (const char*)(Bm + (size_t)(n0 + prow) * K + pc4 * 4);
        const uint32_t rowK4 = (uint32_t)K * 4u;     // bytes per row
        const uint32_t sts0  = (uint32_t)(prow * STRD + pc4 * 8);

        float4 bufA[2][4], bufB[2][4];

        auto LDGR = [&](int c, int r, int pb) {
            uint32_t kb = (uint32_t)c * 256u;
            #pragma unroll
            for (int j = 0; j < 4; j++) {
                uint32_t ro = (uint32_t)(r * 32 + 8 * j) * rowK4 + kb;
                bufA[pb][j] = *(const float4*)(Ab + ro);
                bufB[pb][j] = *(const float4*)(Bb + ro);
            }
        };
        auto SPLITSTS = [&](int s, int r, int pb) {
            char* st = smem + s * STAGE;
            #pragma unroll
            for (int j = 0; j < 4; j++) {
                uint32_t so = sts0 + (uint32_t)(r * 32 + 8 * j) * STRD;
                uint2 h, l;
                split2(bufA[pb][j].x, bufA[pb][j].y, h.x, l.x);
                split2(bufA[pb][j].z, bufA[pb][j].w, h.y, l.y);
                *(uint2*)(st + OFF_AH + so) = h;
                *(uint2*)(st + OFF_AL + so) = l;
                split2(bufB[pb][j].x, bufB[pb][j].y, h.x, l.x);
                split2(bufB[pb][j].z, bufB[pb][j].w, h.y, l.y);
                *(uint2*)(st + OFF_BH + so) = h;
                *(uint2*)(st + OFF_BL + so) = l;
            }
        };
        auto FILL = [&](int s, int c) {     // full 128-row tile, 4 rounds
            LDGR(c, 0, 0);
            LDGR(c, 1, 1);
            SPLITSTS(s, 0, 0);
            LDGR(c, 2, 0);
            SPLITSTS(s, 1, 1);
            LDGR(c, 3, 1);
            SPLITSTS(s, 2, 0);
            SPLITSTS(s, 3, 1);
        };

        FILL(0, 0);                         // prologue: chunk 0 -> stage 0
        __syncthreads();
        #pragma unroll 1
        for (int c = 0; c < nCh; ++c) {
            if (c + 1 < nCh) FILL((c + 1) & 1, c + 1);
            __syncthreads();
        }
        return;                              // producers done (no epilogue)
    }

    // ========================= CONSUMER (warps 0-15) =======================
    const int wm = (wid & 3) * 32;
    const int wn = (wid >> 2) * 32;
    const int a_row = (lane & 15);
    const int a_kc  = (lane >> 4) * 8;
    const int b_row = ((lane >> 4) << 3) + (lane & 7);
    const int b_kc  = ((lane >> 3) & 1) * 8;

    float acc[2][4][4] = {};   // [mt][nb*2+nt][frag]

    __syncthreads();           // matches producer prologue barrier

    #pragma unroll 1
    for (int c = 0; c < nCh; ++c) {
        const uint32_t stb = sbase + (c & 1) * STAGE;
        #pragma unroll
        for (int kk = 0; kk < 64; kk += 16) {
            uint32_t ah[2][4], al[2][4], bh[2][4], bl[2][4];
            #pragma unroll
            for (int mt = 0; mt < 2; mt++) {
                uint32_t ro = (uint32_t)((wm + mt * 16 + a_row) * STRD +
                                         (kk + a_kc) * 2);
                ldsm_x4(ah[mt], stb + OFF_AH + ro);
                ldsm_x4(al[mt], stb + OFF_AL + ro);
            }
            #pragma unroll
            for (int nb = 0; nb < 2; nb++) {
                uint32_t ro = (uint32_t)((wn + nb * 16 + b_row) * STRD +
                                         (kk + b_kc) * 2);
                ldsm_x4(bh[nb], stb + OFF_BH + ro);
                ldsm_x4(bl[nb], stb + OFF_BL + ro);
            }
            // pass 1: hi*hi — 8 independent MMAs
            #pragma unroll
            for (int mt = 0; mt < 2; mt++)
                #pragma unroll
                for (int nb = 0; nb < 2; nb++)
                    #pragma unroll
                    for (int nt = 0; nt < 2; nt++)
                        mma_bf16(acc[mt][nb * 2 + nt], ah[mt],
                                 bh[nb][nt * 2], bh[nb][nt * 2 + 1]);
            // pass 2: hi*lo
            #pragma unroll
            for (int mt = 0; mt < 2; mt++)
                #pragma unroll
                for (int nb = 0; nb < 2; nb++)
                    #pragma unroll
                    for (int nt = 0; nt < 2; nt++)
                        mma_bf16(acc[mt][nb * 2 + nt], ah[mt],
                                 bl[nb][nt * 2], bl[nb][nt * 2 + 1]);
            // pass 3: lo*hi
            #pragma unroll
            for (int mt = 0; mt < 2; mt++)
                #pragma unroll
                for (int nb = 0; nb < 2; nb++)
                    #pragma unroll
                    for (int nt = 0; nt < 2; nt++)
                        mma_bf16(acc[mt][nb * 2 + nt], al[mt],
                                 bh[nb][nt * 2], bh[nb][nt * 2 + 1]);
        }
        __syncthreads();
    }

    // epilogue (consumers only)
    const int g = lane >> 2, cc2 = (lane & 3) * 2;
    #pragma unroll
    for (int mt = 0; mt < 2; mt++) {
        #pragma unroll
        for (int j = 0; j < 4; j++) {
            int row = m0 + wm + mt * 16 + g;
            int col = n0 + wn + j * 8 + cc2;
            float* a4 = acc[mt][j];
            if (relu) {
                a4[0] = fmaxf(a4[0], 0.f); a4[1] = fmaxf(a4[1], 0.f);
                a4[2] = fmaxf(a4[2], 0.f); a4[3] = fmaxf(a4[3], 0.f);
            }
            *(float2*)(C + (size_t)row * ldc + col)       = make_float2(a4[0], a4[1]);
            *(float2*)(C + (size_t)(row + 8) * ldc + col) = make_float2(a4[2], a4[3]);
        }
    }
}

// ---------------------------------------------------------------------------
// q[b][j][h] -> qT[b][h][j]
// ---------------------------------------------------------------------------
__global__ void transpose_q(const float* __restrict__ q, float* __restrict__ qT)
{
    __shared__ float tile[32][33];
    const int b = blockIdx.z;
    const int j0 = blockIdx.x * 32, h0 = blockIdx.y * 32;
    const float* qb = q + (size_t)b * QLEN * HID;
    float* tb = qT + (size_t)b * HID * QLEN;
    #pragma unroll
    for (int r = threadIdx.y; r < 32; r += 8)
        tile[r][threadIdx.x] = qb[(size_t)(j0 + r) * HID + h0 + threadIdx.x];
    __syncthreads();
    #pragma unroll
    for (int r = threadIdx.y; r < 32; r += 8)
        tb[(size_t)(h0 + r) * QLEN + j0 + threadIdx.x] = tile[threadIdx.x][r];
}

// ---------------------------------------------------------------------------
// In-place row softmax over Q with q_mask (True = pad -> -inf).
// ---------------------------------------------------------------------------
__global__ __launch_bounds__(256) void softmax_rows(
    float* __restrict__ sc, const unsigned char* __restrict__ qmask)
{
    const int row = blockIdx.x;
    const int b   = row / PLEN;
    float* s = sc + (size_t)row * QLEN;
    const unsigned char* m = qmask + (size_t)b * QLEN;

    const int t = threadIdx.x;
    float v[4];
    float mx = -INFINITY;
    #pragma unroll
    for (int i = 0; i < 4; i++) {
        int idx = t + i * 256;
        float x = s[idx];
        if (m[idx]) x = -INFINITY;
        v[i] = x;
        mx = fmaxf(mx, x);
    }

    __shared__ float warpred[8];
    __shared__ float bcast;

    #pragma unroll
    for (int o = 16; o; o >>= 1) mx = fmaxf(mx, __shfl_xor_sync(0xffffffffu, mx, o));
    if ((t & 31) == 0) warpred[t >> 5] = mx;
    __syncthreads();
    if (t == 0) {
        float r = warpred[0];
        #pragma unroll
        for (int w = 1; w < 8; w++) r = fmaxf(r, warpred[w]);
        bcast = r;
    }
    __syncthreads();
    mx = bcast;

    float sum = 0.0f;
    #pragma unroll
    for (int i = 0; i < 4; i++) { v[i] = expf(v[i] - mx); sum += v[i]; }
    __syncthreads();

    #pragma unroll
    for (int o = 16; o; o >>= 1) sum += __shfl_xor_sync(0xffffffffu, sum, o);
    if ((t & 31) == 0) warpred[t >> 5] = sum;
    __syncthreads();
    if (t == 0) {
        float r = 0.0f;
        #pragma unroll
        for (int w = 0; w < 8; w++) r += warpred[w];
        bcast = r;
    }
    __syncthreads();
    const float inv = 1.0f / bcast;

    #pragma unroll
    for (int i = 0; i < 4; i++)
        s[t + i * 256] = v[i] * inv;
}

// ---------------------------------------------------------------------------
extern "C" void kernel_launch(void* const* d_in, const int* in_sizes, int n_in,
                              void* d_out, int out_size)
{
    (void)in_sizes; (void)n_in; (void)out_size;
    const float*         k     = (const float*)d_in[0];          // [B, P, H]
    const float*         q     = (const float*)d_in[1];          // [B, Q, H]
    const unsigned char* qmask = (const unsigned char*)d_in[2];  // [B, Q] bool
    const float*         Wk    = (const float*)d_in[3];          // [H, H]
    const float*         Wq    = (const float*)d_in[4];          // [H, H]

    float* ctx    = (float*)d_out;                               // [B, P, H]
    float* alphas = ctx + (size_t)B_ * PLEN * HID;               // [B, P, Q]

    float *pkey, *qkey, *qT;
    cudaGetSymbolAddress((void**)&pkey, g_pkey);
    cudaGetSymbolAddress((void**)&qkey, g_qkey);
    cudaGetSymbolAddress((void**)&qT,   g_qT);

    static int smem_set = 0;
    if (!smem_set) {
        cudaFuncSetAttribute(gemm_3xbf16,
                             cudaFuncAttributeMaxDynamicSharedMemorySize, GSMEM);
        smem_set = 1;
    }

    // 0) qT[b] = q[b]^T
    transpose_q<<<dim3(QLEN / 32, HID / 32, B_), dim3(32, 8)>>>(q, qT);

    // 1) p_key = relu(k @ Wk^T)
    gemm_3xbf16<<<dim3(HID / 128, (B_ * PLEN) / 128, 1), NTHREADS, GSMEM>>>(
        k, Wk, pkey, HID, HID, 1, 0, 0, 0);

    // 2) q_key = relu(q @ Wq^T)
    gemm_3xbf16<<<dim3(HID / 128, (B_ * QLEN) / 128, 1), NTHREADS, GSMEM>>>(
        q, Wq, qkey, HID, HID, 1, 0, 0, 0);

    // 3) scores[b] = p_key[b] @ q_key[b]^T  -> raw into alphas region
    gemm_3xbf16<<<dim3(QLEN / 128, PLEN / 128, B_), NTHREADS, GSMEM>>>(
        pkey, qkey, alphas, HID, QLEN, 0,
        (size_t)PLEN * HID, (size_t)QLEN * HID, (size_t)PLEN * QLEN);

    // 4) softmax in place
    softmax_rows<<<B_ * PLEN, 256>>>(alphas, qmask);

    // 5) ctx[b] = alphas[b] @ q[b] == alphas[b] @ (qT[b])^T  (NT)
    gemm_3xbf16<<<dim3(HID / 128, PLEN / 128, B_), NTHREADS, GSMEM>>>(
        alphas, qT, ctx, QLEN, HID, 0,
        (size_t)PLEN * QLEN, (size_t)HID * QLEN, (size_t)PLEN * HID);
}

// round 11
// speedup vs baseline: 1.5560x; 1.1107x over previous
#include <cuda_runtime.h>
#include <cuda_bf16.h>
#include <math.h>
#include <stdint.h>

#define B_   8
#define PLEN 2048
#define QLEN 1024
#define HID  1024

// Scratch (__device__ globals: allocation-free rule)
__device__ float g_pkey[(size_t)B_ * PLEN * HID];   // 64 MB
__device__ float g_qkey[(size_t)B_ * QLEN * HID];   // 32 MB
__device__ float g_qT  [(size_t)B_ * HID  * QLEN];  // 32 MB

// ---------------------------------------------------------------------------
// helpers
// ---------------------------------------------------------------------------
__device__ __forceinline__ uint32_t smem_u32(const void* p) {
    return (uint32_t)__cvta_generic_to_shared(p);
}

// split two fp32 into packed bf16x2 (hi plane, lo plane); element0 in low half
__device__ __forceinline__ void split2(float x0, float x1,
                                       uint32_t& hi, uint32_t& lo) {
    uint32_t h;
    asm("cvt.rn.bf16x2.f32 %0, %1, %2;" : "=r"(h) : "f"(x1), "f"(x0));
    float h0 = __uint_as_float(h << 16);           // bf16 -> f32 via shift
    float h1 = __uint_as_float(h & 0xffff0000u);
    uint32_t l;
    asm("cvt.rn.bf16x2.f32 %0, %1, %2;" : "=r"(l) : "f"(x1 - h1), "f"(x0 - h0));
    hi = h; lo = l;
}

__device__ __forceinline__ void ldsm_x4(uint32_t r[4], uint32_t addr) {
    asm volatile("ldmatrix.sync.aligned.m8n8.x4.shared.b16 {%0,%1,%2,%3}, [%4];"
                 : "=r"(r[0]), "=r"(r[1]), "=r"(r[2]), "=r"(r[3]) : "r"(addr));
}

__device__ __forceinline__ void mma_bf16(float c[4], const uint32_t a[4],
                                         uint32_t b0, uint32_t b1) {
    asm volatile(
        "mma.sync.aligned.m16n8k16.row.col.f32.bf16.bf16.f32 "
        "{%0,%1,%2,%3}, {%4,%5,%6,%7}, {%8,%9}, {%0,%1,%2,%3};"
        : "+f"(c[0]), "+f"(c[1]), "+f"(c[2]), "+f"(c[3])
        : "r"(a[0]), "r"(a[1]), "r"(a[2]), "r"(a[3]), "r"(b0), "r"(b1));
}

// ---------------------------------------------------------------------------
// 3xBF16 NT GEMM, warp-specialized.
// C[m,n] = (opt relu) sum_k A[m,k]*B[n,k], fp32 in/out.
// CTA tile 128x128, BK=64, two-stage split-bf16 smem pipeline.
// 384 threads: warps 0-7 consumers (2Mx4N grid, 64x32 warp tile, pure
// ldsm+MMA — bigger tile cuts smem read amplification 25%); warps 8-11
// producers (LDG -> split -> STS for next chunk). One barrier per chunk.
// ---------------------------------------------------------------------------
#define STRD   144      // bytes per smem row: 64 bf16 (128B) + 16B pad
#define PLANE  18432    // 128 rows * 144
#define OFF_AH 0
#define OFF_AL PLANE
#define OFF_BH (2 * PLANE)
#define OFF_BL (3 * PLANE)
#define STAGE  (4 * PLANE)      // 73728
#define GSMEM  (2 * STAGE)      // 147456
#define NTHREADS 384

__global__ __launch_bounds__(NTHREADS, 1) void gemm_3xbf16(
    const float* __restrict__ A, const float* __restrict__ Bm,
    float* __restrict__ C, int K, int ldc, int relu,
    size_t sA, size_t sB, size_t sC)
{
    extern __shared__ __align__(128) char smem[];
    const uint32_t sbase = smem_u32(smem);
    const int tid  = threadIdx.x;
    const int lane = tid & 31;
    const int wid  = tid >> 5;
    const int m0 = blockIdx.y * 128;
    const int n0 = blockIdx.x * 128;
    A  += (size_t)blockIdx.z * sA;
    Bm += (size_t)blockIdx.z * sB;
    C  += (size_t)blockIdx.z * sC;

    const int nCh = K / 64;

    if (wid >= 8) {
        // ===================== PRODUCER (warps 8-11, 128 threads) ==========
        const int pt = tid - 256;           // 0..127
        const int prow = pt >> 4;           // 0..7
        const int pc4  = pt & 15;           // 0..15 (float4 column)
        const char* Ab = (const char*)(A  + (size_t)(m0 + prow) * K + pc4 * 4);
        const char* Bb = (const char*)(Bm + (size_t)(n0 + prow) * K + pc4 * 4);
        const uint32_t rowK4 = (uint32_t)K * 4u;     // bytes per row
        const uint32_t sts0  = (uint32_t)(prow * STRD + pc4 * 8);

        float4 bufA[2][4], bufB[2][4];

        auto LDGR = [&](int c, int r, int pb) {
            uint32_t kb = (uint32_t)c * 256u;
            #pragma unroll
            for (int j = 0; j < 4; j++) {
                uint32_t ro = (uint32_t)(r * 32 + 8 * j) * rowK4 + kb;
                bufA[pb][j] = *(const float4*)(Ab + ro);
                bufB[pb][j] = *(const float4*)(Bb + ro);
            }
        };
        auto SPLITSTS = [&](int s, int r, int pb) {
            char* st = smem + s * STAGE;
            #pragma unroll
            for (int j = 0; j < 4; j++) {
                uint32_t so = sts0 + (uint32_t)(r * 32 + 8 * j) * STRD;
                uint2 h, l;
                split2(bufA[pb][j].x, bufA[pb][j].y, h.x, l.x);
                split2(bufA[pb][j].z, bufA[pb][j].w, h.y, l.y);
                *(uint2*)(st + OFF_AH + so) = h;
                *(uint2*)(st + OFF_AL + so) = l;
                split2(bufB[pb][j].x, bufB[pb][j].y, h.x, l.x);
                split2(bufB[pb][j].z, bufB[pb][j].w, h.y, l.y);
                *(uint2*)(st + OFF_BH + so) = h;
                *(uint2*)(st + OFF_BL + so) = l;
            }
        };
        auto FILL = [&](int s, int c) {     // full 128-row tile, 4 rounds
            LDGR(c, 0, 0);
            LDGR(c, 1, 1);
            SPLITSTS(s, 0, 0);
            LDGR(c, 2, 0);
            SPLITSTS(s, 1, 1);
            LDGR(c, 3, 1);
            SPLITSTS(s, 2, 0);
            SPLITSTS(s, 3, 1);
        };

        FILL(0, 0);                         // prologue: chunk 0 -> stage 0
        __syncthreads();
        #pragma unroll 1
        for (int c = 0; c < nCh; ++c) {
            if (c + 1 < nCh) FILL((c + 1) & 1, c + 1);
            __syncthreads();
        }
        return;                              // producers done (no epilogue)
    }

    // ========================= CONSUMER (warps 0-7) ========================
    // warp grid: 2(M) x 4(N); warp tile 64x32
    const int wm = (wid & 1) * 64;
    const int wn = (wid >> 1) * 32;
    const int a_row = (lane & 15);
    const int a_kc  = (lane >> 4) * 8;
    const int b_row = ((lane >> 4) << 3) + (lane & 7);
    const int b_kc  = ((lane >> 3) & 1) * 8;

    float acc[4][4][4] = {};   // [mt][nb*2+nt][frag]

    __syncthreads();           // matches producer prologue barrier

    #pragma unroll 1
    for (int c = 0; c < nCh; ++c) {
        const uint32_t stb = sbase + (c & 1) * STAGE;
        #pragma unroll
        for (int kk = 0; kk < 64; kk += 16) {
            uint32_t ah[4][4], al[4][4], bh[2][4], bl[2][4];
            #pragma unroll
            for (int mt = 0; mt < 4; mt++) {
                uint32_t ro = (uint32_t)((wm + mt * 16 + a_row) * STRD +
                                         (kk + a_kc) * 2);
                ldsm_x4(ah[mt], stb + OFF_AH + ro);
                ldsm_x4(al[mt], stb + OFF_AL + ro);
            }
            #pragma unroll
            for (int nb = 0; nb < 2; nb++) {
                uint32_t ro = (uint32_t)((wn + nb * 16 + b_row) * STRD +
                                         (kk + b_kc) * 2);
                ldsm_x4(bh[nb], stb + OFF_BH + ro);
                ldsm_x4(bl[nb], stb + OFF_BL + ro);
            }
            // pass 1: hi*hi — 16 independent MMAs
            #pragma unroll
            for (int mt = 0; mt < 4; mt++)
                #pragma unroll
                for (int nb = 0; nb < 2; nb++)
                    #pragma unroll
                    for (int nt = 0; nt < 2; nt++)
                        mma_bf16(acc[mt][nb * 2 + nt], ah[mt],
                                 bh[nb][nt * 2], bh[nb][nt * 2 + 1]);
            // pass 2: hi*lo
            #pragma unroll
            for (int mt = 0; mt < 4; mt++)
                #pragma unroll
                for (int nb = 0; nb < 2; nb++)
                    #pragma unroll
                    for (int nt = 0; nt < 2; nt++)
                        mma_bf16(acc[mt][nb * 2 + nt], ah[mt],
                                 bl[nb][nt * 2], bl[nb][nt * 2 + 1]);
            // pass 3: lo*hi
            #pragma unroll
            for (int mt = 0; mt < 4; mt++)
                #pragma unroll
                for (int nb = 0; nb < 2; nb++)
                    #pragma unroll
                    for (int nt = 0; nt < 2; nt++)
                        mma_bf16(acc[mt][nb * 2 + nt], al[mt],
                                 bh[nb][nt * 2], bh[nb][nt * 2 + 1]);
        }
        __syncthreads();
    }

    // epilogue (consumers only)
    const int g = lane >> 2, cc2 = (lane & 3) * 2;
    #pragma unroll
    for (int mt = 0; mt < 4; mt++) {
        #pragma unroll
        for (int j = 0; j < 4; j++) {
            int row = m0 + wm + mt * 16 + g;
            int col = n0 + wn + j * 8 + cc2;
            float* a4 = acc[mt][j];
            if (relu) {
                a4[0] = fmaxf(a4[0], 0.f); a4[1] = fmaxf(a4[1], 0.f);
                a4[2] = fmaxf(a4[2], 0.f); a4[3] = fmaxf(a4[3], 0.f);
            }
            *(float2*)(C + (size_t)row * ldc + col)       = make_float2(a4[0], a4[1]);
            *(float2*)(C + (size_t)(row + 8) * ldc + col) = make_float2(a4[2], a4[3]);
        }
    }
}

// ---------------------------------------------------------------------------
// q[b][j][h] -> qT[b][h][j]
// ---------------------------------------------------------------------------
__global__ void transpose_q(const float* __restrict__ q, float* __restrict__ qT)
{
    __shared__ float tile[32][33];
    const int b = blockIdx.z;
    const int j0 = blockIdx.x * 32, h0 = blockIdx.y * 32;
    const float* qb = q + (size_t)b * QLEN * HID;
    float* tb = qT + (size_t)b * HID * QLEN;
    #pragma unroll
    for (int r = threadIdx.y; r < 32; r += 8)
        tile[r][threadIdx.x] = qb[(size_t)(j0 + r) * HID + h0 + threadIdx.x];
    __syncthreads();
    #pragma unroll
    for (int r = threadIdx.y; r < 32; r += 8)
        tb[(size_t)(h0 + r) * QLEN + j0 + threadIdx.x] = tile[threadIdx.x][r];
}

// ---------------------------------------------------------------------------
// In-place row softmax over Q with q_mask (True = pad -> -inf).
// ---------------------------------------------------------------------------
__global__ __launch_bounds__(256) void softmax_rows(
    float* __restrict__ sc, const unsigned char* __restrict__ qmask)
{
    const int row = blockIdx.x;
    const int b   = row / PLEN;
    float* s = sc + (size_t)row * QLEN;
    const unsigned char* m = qmask + (size_t)b * QLEN;

    const int t = threadIdx.x;
    float v[4];
    float mx = -INFINITY;
    #pragma unroll
    for (int i = 0; i < 4; i++) {
        int idx = t + i * 256;
        float x = s[idx];
        if (m[idx]) x = -INFINITY;
        v[i] = x;
        mx = fmaxf(mx, x);
    }

    __shared__ float warpred[8];
    __shared__ float bcast;

    #pragma unroll
    for (int o = 16; o; o >>= 1) mx = fmaxf(mx, __shfl_xor_sync(0xffffffffu, mx, o));
    if ((t & 31) == 0) warpred[t >> 5] = mx;
    __syncthreads();
    if (t == 0) {
        float r = warpred[0];
        #pragma unroll
        for (int w = 1; w < 8; w++) r = fmaxf(r, warpred[w]);
        bcast = r;
    }
    __syncthreads();
    mx = bcast;

    float sum = 0.0f;
    #pragma unroll
    for (int i = 0; i < 4; i++) { v[i] = expf(v[i] - mx); sum += v[i]; }
    __syncthreads();

    #pragma unroll
    for (int o = 16; o; o >>= 1) sum += __shfl_xor_sync(0xffffffffu, sum, o);
    if ((t & 31) == 0) warpred[t >> 5] = sum;
    __syncthreads();
    if (t == 0) {
        float r = 0.0f;
        #pragma unroll
        for (int w = 0; w < 8; w++) r += warpred[w];
        bcast = r;
    }
    __syncthreads();
    const float inv = 1.0f / bcast;

    #pragma unroll
    for (int i = 0; i < 4; i++)
        s[t + i * 256] = v[i] * inv;
}

// ---------------------------------------------------------------------------
extern "C" void kernel_launch(void* const* d_in, const int* in_sizes, int n_in,
                              void* d_out, int out_size)
{
    (void)in_sizes; (void)n_in; (void)out_size;
    const float*         k     = (const float*)d_in[0];          // [B, P, H]
    const float*         q     = (const float*)d_in[1];          // [B, Q, H]
    const unsigned char* qmask = (const unsigned char*)d_in[2];  // [B, Q] bool
    const float*         Wk    = (const float*)d_in[3];          // [H, H]
    const float*         Wq    = (const float*)d_in[4];          // [H, H]

    float* ctx    = (float*)d_out;                               // [B, P, H]
    float* alphas = ctx + (size_t)B_ * PLEN * HID;               // [B, P, Q]

    float *pkey, *qkey, *qT;
    cudaGetSymbolAddress((void**)&pkey, g_pkey);
    cudaGetSymbolAddress((void**)&qkey, g_qkey);
    cudaGetSymbolAddress((void**)&qT,   g_qT);

    static int smem_set = 0;
    if (!smem_set) {
        cudaFuncSetAttribute(gemm_3xbf16,
                             cudaFuncAttributeMaxDynamicSharedMemorySize, GSMEM);
        smem_set = 1;
    }

    // 0) qT[b] = q[b]^T
    transpose_q<<<dim3(QLEN / 32, HID / 32, B_), dim3(32, 8)>>>(q, qT);

    // 1) p_key = relu(k @ Wk^T)
    gemm_3xbf16<<<dim3(HID / 128, (B_ * PLEN) / 128, 1), NTHREADS, GSMEM>>>(
        k, Wk, pkey, HID, HID, 1, 0, 0, 0);

    // 2) q_key = relu(q @ Wq^T)
    gemm_3xbf16<<<dim3(HID / 128, (B_ * QLEN) / 128, 1), NTHREADS, GSMEM>>>(
        q, Wq, qkey, HID, HID, 1, 0, 0, 0);

    // 3) scores[b] = p_key[b] @ q_key[b]^T  -> raw into alphas region
    gemm_3xbf16<<<dim3(QLEN / 128, PLEN / 128, B_), NTHREADS, GSMEM>>>(
        pkey, qkey, alphas, HID, QLEN, 0,
        (size_t)PLEN * HID, (size_t)QLEN * HID, (size_t)PLEN * QLEN);

    // 4) softmax in place
    softmax_rows<<<B_ * PLEN, 256>>>(alphas, qmask);

    // 5) ctx[b] = alphas[b] @ q[b] == alphas[b] @ (qT[b])^T  (NT)
    gemm_3xbf16<<<dim3(HID / 128, PLEN / 128, B_), NTHREADS, GSMEM>>>(
        alphas, qT, ctx, QLEN, HID, 0,
        (size_t)PLEN * QLEN, (size_t)HID * QLEN, (size_t)PLEN * HID);
}